// round 6
// baseline (speedup 1.0000x reference)
#include <cuda_runtime.h>
#include <cuda_fp16.h>
#include <math.h>

typedef unsigned int u32;

#define DID 4096
#define EXP 64
#define NE 128          // 64 clean + 64 noise output columns
#define MT 128          // rows per CTA
#define KC 64           // k per chunk
#define NCH (DID / KC)  // 64 chunks
#define THREADS 512
#define RSCALE 4096.0f
#define INV_RSCALE (1.0f / 4096.0f)

// ---------------- global scratch ----------------
__device__ unsigned short g_w0[NE][DID];   // fp16 main limb of [clean|noise] weights, [n][k]
__device__ unsigned short g_w1[NE][DID];   // fp16 residual limb (pre-scaled by 4096)
__device__ float g_importance[EXP];
__device__ int   g_load[EXP];
__device__ int   g_count;

// ---------------- smem layout (dynamic) ----------------
// [0, 64K)        x fp32 staging, 2 stages x 32KB
// [64K, 96K)      A fp16 limb tiles (single stage): limb x 16KB
// [96K, 160K)     B fp16 limb tiles: (stage,limb) x 16KB
// [160K, +1K)     control
// logits overlay [128][132] f32 = 67584B reuses [0, 67584) after the mainloop.
#define XS_OFF(s)   ((s) * 32768)
#define A_OFF(l)    (65536 + (l) * 16384)
#define B_OFF(s, l) (98304 + ((s) * 2 + (l)) * 16384)
#define CTRL_OFF    163840
#define SMEM_BYTES  (163840 + 1024)
#define LSTRIDE     132

// ---------------- PTX helpers ----------------
__device__ __forceinline__ u32 smem_u32(const void* p) {
    u32 a;
    asm("{ .reg .u64 t; cvta.to.shared.u64 t, %1; cvt.u32.u64 %0, t; }" : "=r"(a) : "l"(p));
    return a;
}
__device__ __forceinline__ void cp16(u32 dst, const void* src) {
    asm volatile("cp.async.cg.shared.global [%0], [%1], 16;" :: "r"(dst), "l"(src));
}
#define CP_COMMIT() asm volatile("cp.async.commit_group;")
#define CP_WAIT1()  asm volatile("cp.async.wait_group 1;")
#define CP_WAIT0()  asm volatile("cp.async.wait_group 0;")

__device__ __forceinline__ void ldsm4(u32 addr, u32& r0, u32& r1, u32& r2, u32& r3) {
    asm volatile("ldmatrix.sync.aligned.m8n8.x4.shared.b16 {%0,%1,%2,%3}, [%4];"
                 : "=r"(r0), "=r"(r1), "=r"(r2), "=r"(r3) : "r"(addr));
}
// fp32-accumulate HMMA (main term)
__device__ __forceinline__ void mma_f32(float* d, const u32* a, const u32* b) {
    asm volatile("mma.sync.aligned.m16n8k16.row.col.f32.f16.f16.f32 "
                 "{%0,%1,%2,%3}, {%4,%5,%6,%7}, {%8,%9}, {%0,%1,%2,%3};"
                 : "+f"(d[0]), "+f"(d[1]), "+f"(d[2]), "+f"(d[3])
                 : "r"(a[0]), "r"(a[1]), "r"(a[2]), "r"(a[3]), "r"(b[0]), "r"(b[1]));
}
// fp16-accumulate HMMA (cross terms; values ~|15| max, rounding folded by /4096)
__device__ __forceinline__ void mma_f16(u32* d, const u32* a, const u32* b) {
    asm volatile("mma.sync.aligned.m16n8k16.row.col.f16.f16.f16.f16 "
                 "{%0,%1}, {%2,%3,%4,%5}, {%6,%7}, {%0,%1};"
                 : "+r"(d[0]), "+r"(d[1])
                 : "r"(a[0]), "r"(a[1]), "r"(a[2]), "r"(a[3]), "r"(b[0]), "r"(b[1]));
}

__device__ __forceinline__ void split2(float v, unsigned short& h0, unsigned short& h1) {
    __half a = __float2half_rn(v);
    float r = (v - __half2float(a)) * RSCALE;   // exact residual, exact pow2 scale
    __half b = __float2half_rn(r);
    h0 = __half_as_ushort(a);
    h1 = __half_as_ushort(b);
}

__device__ __forceinline__ float softplus_f(float z) {
    return (z > 0.0f) ? (z + log1pf(expf(-z))) : log1pf(expf(z));
}

// ---------------- weight pre-split kernel ----------------
__global__ void __launch_bounds__(256) split_w_kernel(const float* __restrict__ gw,
                                                      const float* __restrict__ wn) {
    __shared__ float t[64][65];
    int k0 = blockIdx.x * 64;
    for (int half = 0; half < 2; half++) {
        const float* src = half ? wn : gw;
        __syncthreads();
        for (int i = threadIdx.x; i < 64 * 64; i += 256) {
            int kk = i >> 6, n = i & 63;
            t[n][kk] = src[(size_t)(k0 + kk) * EXP + n];
        }
        __syncthreads();
        for (int i = threadIdx.x; i < 64 * 16; i += 256) {
            int n = i >> 4, c = i & 15;
            int nn = half * 64 + n;
            unsigned short h0[4], h1[4];
            #pragma unroll
            for (int j = 0; j < 4; j++) split2(t[n][c * 4 + j], h0[j], h1[j]);
            *(uint2*)&g_w0[nn][k0 + c * 4] =
                make_uint2((u32)h0[0] | ((u32)h0[1] << 16), (u32)h0[2] | ((u32)h0[3] << 16));
            *(uint2*)&g_w1[nn][k0 + c * 4] =
                make_uint2((u32)h1[0] | ((u32)h1[1] << 16), (u32)h1[2] | ((u32)h1[3] << 16));
        }
    }
}

// ---------------- main router kernel ----------------
__global__ void __launch_bounds__(THREADS, 1)
router_kernel(const float* __restrict__ x,
              const float* __restrict__ gate_b,
              const float* __restrict__ noise,
              float* __restrict__ out, int B, int nblocks)
{
    extern __shared__ __align__(1024) char smc[];
    const u32 sb = smem_u32(smc);
    float* bias_s  = (float*)(smc + CTRL_OFF);
    float* imp_s   = (float*)(smc + CTRL_OFF + 256);
    int*   load_s  = (int*)(smc + CTRL_OFF + 512);
    int*   is_last = (int*)(smc + CTRL_OFF + 768);

    const int tid = threadIdx.x;
    const int wid = tid >> 5, lane = tid & 31;
    const int m0 = blockIdx.x * MT;
    const int mwarp = wid & 3;        // 4 row groups of 32
    const int nwarp = wid >> 2;       // 4 col groups of 32

    if (tid < EXP) { bias_s[tid] = gate_b[tid]; imp_s[tid] = 0.0f; load_s[tid] = 0; }

    float accM[2][4][4];   // fp32 main accumulator, 32 regs
    u32   accC[2][4][2];   // fp16x2 cross accumulator, 16 regs
    #pragma unroll
    for (int mt = 0; mt < 2; mt++)
        #pragma unroll
        for (int nt = 0; nt < 4; nt++) {
            #pragma unroll
            for (int r = 0; r < 4; r++) accM[mt][nt][r] = 0.0f;
            accC[mt][nt][0] = 0u; accC[mt][nt][1] = 0u;
        }

    // ldmatrix lane constants
    const int a_row = lane & 15;
    const int a_kb  = lane >> 4;
    const int b_row = (lane & 7) + ((lane >> 4) & 1) * 8;
    const int b_kb  = (lane >> 3) & 1;

    // ---- prologue: issue chunk 0 into stage 0 ----
    {
        #pragma unroll
        for (int i = 0; i < 4; i++) {
            int u = tid + i * 512;
            int row = u >> 4, cu = u & 15;
            cp16(sb + XS_OFF(0) + u * 16, x + (size_t)(m0 + row) * DID + cu * 4);
        }
        #pragma unroll
        for (int i = 0; i < 2; i++) {
            int u = tid + i * 512;
            int n = u >> 3, cu = u & 7;
            u32 sw = (u32)(n * 128 + ((cu ^ (n & 7)) * 16));
            cp16(sb + B_OFF(0, 0) + sw, &g_w0[n][cu * 8]);
            cp16(sb + B_OFF(0, 1) + sw, &g_w1[n][cu * 8]);
        }
        CP_COMMIT();
    }

    for (int kc = 0; kc < NCH; kc++) {
        const int s = kc & 1;
        __syncthreads();   // all warps done with mma(kc-1): A tile free, stage s^1 free

        if (kc + 1 < NCH) {
            const int k0n = (kc + 1) * KC;
            #pragma unroll
            for (int i = 0; i < 4; i++) {
                int u = tid + i * 512;
                int row = u >> 4, cu = u & 15;
                cp16(sb + XS_OFF(s ^ 1) + u * 16, x + (size_t)(m0 + row) * DID + k0n + cu * 4);
            }
            #pragma unroll
            for (int i = 0; i < 2; i++) {
                int u = tid + i * 512;
                int n = u >> 3, cu = u & 7;
                u32 sw = (u32)(n * 128 + ((cu ^ (n & 7)) * 16));
                cp16(sb + B_OFF(s ^ 1, 0) + sw, &g_w0[n][k0n + cu * 8]);
                cp16(sb + B_OFF(s ^ 1, 1) + sw, &g_w1[n][k0n + cu * 8]);
            }
            CP_COMMIT();
            CP_WAIT1();   // chunk kc arrived
        } else {
            CP_WAIT0();
        }

        // convert x fp32 -> 2 fp16 limbs into single-stage A tiles
        #pragma unroll
        for (int i = 0; i < 4; i++) {
            int u = tid + i * 512;
            int row = u >> 4, c = u & 15;
            float4 v = *(const float4*)(smc + XS_OFF(s) + u * 16);
            unsigned short h0[4], h1[4];
            split2(v.x, h0[0], h1[0]);
            split2(v.y, h0[1], h1[1]);
            split2(v.z, h0[2], h1[2]);
            split2(v.w, h0[3], h1[3]);
            u32 off = (u32)(row * 128 + (((c >> 1) ^ (row & 7)) * 16) + (c & 1) * 8);
            *(uint2*)(smc + A_OFF(0) + off) =
                make_uint2((u32)h0[0] | ((u32)h0[1] << 16), (u32)h0[2] | ((u32)h0[3] << 16));
            *(uint2*)(smc + A_OFF(1) + off) =
                make_uint2((u32)h1[0] | ((u32)h1[1] << 16), (u32)h1[2] | ((u32)h1[3] << 16));
        }
        __syncthreads();

        // ---- mma over this chunk: 4 k-steps of 16 ----
        const u32 ab0 = sb + A_OFF(0), ab1 = sb + A_OFF(1);
        const u32 bb0 = sb + B_OFF(s, 0), bb1 = sb + B_OFF(s, 1);
        #pragma unroll
        for (int ks = 0; ks < 4; ks++) {
            u32 A0[2][4], A1[2][4];
            #pragma unroll
            for (int mt = 0; mt < 2; mt++) {
                int row = mwarp * 32 + mt * 16 + a_row;
                u32 off = (u32)(row * 128 + (((ks * 2 + a_kb) ^ (row & 7)) * 16));
                ldsm4(ab0 + off, A0[mt][0], A0[mt][1], A0[mt][2], A0[mt][3]);
                ldsm4(ab1 + off, A1[mt][0], A1[mt][1], A1[mt][2], A1[mt][3]);
            }
            u32 B0[4][2], B1[4][2];
            #pragma unroll
            for (int p = 0; p < 2; p++) {
                int n = nwarp * 32 + p * 16 + b_row;
                u32 off = (u32)(n * 128 + (((ks * 2 + b_kb) ^ (n & 7)) * 16));
                u32 r0, r1, r2, r3;
                ldsm4(bb0 + off, r0, r1, r2, r3);
                B0[p * 2][0] = r0; B0[p * 2][1] = r1; B0[p * 2 + 1][0] = r2; B0[p * 2 + 1][1] = r3;
                ldsm4(bb1 + off, r0, r1, r2, r3);
                B1[p * 2][0] = r0; B1[p * 2][1] = r1; B1[p * 2 + 1][0] = r2; B1[p * 2 + 1][1] = r3;
            }
            #pragma unroll
            for (int mt = 0; mt < 2; mt++)
                #pragma unroll
                for (int nt = 0; nt < 4; nt++) {
                    mma_f32(accM[mt][nt], A0[mt], B0[nt]);
                    mma_f16(accC[mt][nt], A0[mt], B1[nt]);
                    mma_f16(accC[mt][nt], A1[mt], B0[nt]);
                }
        }
    }

    __syncthreads();

    // ---- write combined logits to smem overlay [128][LSTRIDE] ----
    float* lsm = (float*)smc;
    {
        const int gid = lane >> 2, tig = lane & 3;
        #pragma unroll
        for (int mt = 0; mt < 2; mt++)
            #pragma unroll
            for (int nt = 0; nt < 4; nt++) {
                int r0 = mwarp * 32 + mt * 16 + gid;
                int cc = nwarp * 32 + nt * 8 + tig * 2;
                float2 c0 = __half22float2(*(__half2*)&accC[mt][nt][0]);
                float2 c1 = __half22float2(*(__half2*)&accC[mt][nt][1]);
                float f0 = fmaf(c0.x, INV_RSCALE, accM[mt][nt][0]);
                float f1 = fmaf(c0.y, INV_RSCALE, accM[mt][nt][1]);
                float f2 = fmaf(c1.x, INV_RSCALE, accM[mt][nt][2]);
                float f3 = fmaf(c1.y, INV_RSCALE, accM[mt][nt][3]);
                *(float2*)&lsm[r0 * LSTRIDE + cc]       = make_float2(f0, f1);
                *(float2*)&lsm[(r0 + 8) * LSTRIDE + cc] = make_float2(f2, f3);
            }
    }
    __syncthreads();

    // ---- epilogue: warps 0-3, one row per lane ----
    if (wid < 4) {
        const int rloc = wid * 32 + lane;
        const int row = m0 + rloc;
        const float* nrow = noise + (size_t)row * EXP;
        float l[64];
        #pragma unroll
        for (int e = 0; e < 64; e += 4) {
            float4 cl = *(const float4*)&lsm[rloc * LSTRIDE + e];
            float4 nl = *(const float4*)&lsm[rloc * LSTRIDE + 64 + e];
            float4 nz = *(const float4*)(nrow + e);
            l[e + 0] = fmaf(nz.x, softplus_f(nl.x), cl.x + bias_s[e + 0]);
            l[e + 1] = fmaf(nz.y, softplus_f(nl.y), cl.y + bias_s[e + 1]);
            l[e + 2] = fmaf(nz.z, softplus_f(nl.z), cl.z + bias_s[e + 2]);
            l[e + 3] = fmaf(nz.w, softplus_f(nl.w), cl.w + bias_s[e + 3]);
        }

        // top-2, lowest index wins ties (matches jax.lax.top_k)
        float v1 = -INFINITY, v2 = -INFINITY;
        int i1 = -1, i2 = -1;
        #pragma unroll
        for (int e = 0; e < 64; e++) {
            float le = l[e];
            if (le > v1) { v2 = v1; i2 = i1; v1 = le; i1 = e; }
            else if (le > v2) { v2 = le; i2 = e; }
        }

        // full softmax for importance
        float esum = 0.0f;
        #pragma unroll
        for (int e = 0; e < 64; e++) { l[e] = expf(l[e] - v1); esum += l[e]; }
        float inv = 1.0f / esum;

        #pragma unroll
        for (int e = 0; e < 64; e++) {
            float p = l[e] * inv;
            p += __shfl_xor_sync(0xffffffffu, p, 16);
            p += __shfl_xor_sync(0xffffffffu, p, 8);
            p += __shfl_xor_sync(0xffffffffu, p, 4);
            p += __shfl_xor_sync(0xffffffffu, p, 2);
            p += __shfl_xor_sync(0xffffffffu, p, 1);
            if (lane == 0) atomicAdd(&imp_s[e], p);
        }

        float e21 = expf(v2 - v1);
        float g1 = 1.0f / (1.0f + e21);
        float g2 = e21 * g1;
        *(float2*)(out + (size_t)row * 2) = make_float2(g1, g2);
        *(float2*)(out + (size_t)B * 2 + (size_t)row * 2) = make_float2((float)i1, (float)i2);
        atomicAdd(&load_s[i1], 1);
        atomicAdd(&load_s[i2], 1);
    }
    __syncthreads();

    if (tid < EXP) {
        atomicAdd(&g_importance[tid], imp_s[tid]);
        atomicAdd(&g_load[tid], load_s[tid]);
    }

    // last CTA: finalize aux loss + reset globals for the next graph replay
    __threadfence();
    if (tid == 0) {
        int c = atomicAdd(&g_count, 1);
        *is_last = (c == nblocks - 1) ? 1 : 0;
    }
    __syncthreads();
    if (*is_last) {
        if (tid < EXP) imp_s[tid] = g_importance[tid] * (float)g_load[tid];
        __syncthreads();
        if (tid == 0) {
            float tot = 0.0f;
            #pragma unroll
            for (int i = 0; i < EXP; i++) tot += imp_s[i];
            out[(size_t)B * 4] = tot * (float)EXP;   // mean * E^2 = sum * E
            g_count = 0;
        }
        if (tid < EXP) { g_importance[tid] = 0.0f; g_load[tid] = 0; }
    }
}

extern "C" void kernel_launch(void* const* d_in, const int* in_sizes, int n_in,
                              void* d_out, int out_size) {
    const float* x       = (const float*)d_in[0];
    const float* gate_w  = (const float*)d_in[1];
    const float* gate_b  = (const float*)d_in[2];
    const float* w_noise = (const float*)d_in[3];
    const float* noise   = (const float*)d_in[4];
    float* out = (float*)d_out;

    int B = in_sizes[0] / DID;
    int nblocks = B / MT;

    cudaFuncSetAttribute(router_kernel, cudaFuncAttributeMaxDynamicSharedMemorySize, SMEM_BYTES);

    split_w_kernel<<<DID / 64, 256>>>(gate_w, w_noise);
    router_kernel<<<nblocks, THREADS, SMEM_BYTES>>>(x, gate_b, noise, out, B, nblocks);
}

// round 7
// speedup vs baseline: 1.0030x; 1.0030x over previous
#include <cuda_runtime.h>
#include <cuda_fp16.h>
#include <math.h>

typedef unsigned int u32;

#define DID 4096
#define EXP 64
#define NE 128          // 64 clean + 64 noise output columns
#define MT 128          // rows per CTA
#define KC 64           // k per chunk
#define NCH (DID / KC)  // 64 chunks
#define THREADS 512
#define RSCALE 4096.0f
#define INV_RSCALE (1.0f / 4096.0f)

// ---------------- global scratch ----------------
__device__ unsigned short g_w0[NE][DID];   // fp16 main limb of [clean|noise] weights, [n][k]
__device__ unsigned short g_w1[NE][DID];   // fp16 residual limb (pre-scaled by 4096)
__device__ float g_importance[EXP];
__device__ int   g_load[EXP];
__device__ int   g_count;

// ---------------- smem layout (dynamic) ----------------
// [0, 64K)        x fp32 staging, 2 stages x 32KB
// [64K, 96K)      A fp16 limb tiles (single stage): limb x 16KB
// [96K, 160K)     B fp16 limb tiles: (stage,limb) x 16KB
// [160K, +1K)     control
// logits overlay [128][132] f32 = 67584B reuses [0, 67584) after the mainloop.
#define XS_OFF(s)   ((s) * 32768)
#define A_OFF(l)    (65536 + (l) * 16384)
#define B_OFF(s, l) (98304 + ((s) * 2 + (l)) * 16384)
#define CTRL_OFF    163840
#define SMEM_BYTES  (163840 + 1024)
#define LSTRIDE     132

// ---------------- PTX helpers ----------------
__device__ __forceinline__ u32 smem_u32(const void* p) {
    u32 a;
    asm("{ .reg .u64 t; cvta.to.shared.u64 t, %1; cvt.u32.u64 %0, t; }" : "=r"(a) : "l"(p));
    return a;
}
__device__ __forceinline__ void cp16(u32 dst, const void* src) {
    asm volatile("cp.async.cg.shared.global [%0], [%1], 16;" :: "r"(dst), "l"(src));
}
#define CP_COMMIT() asm volatile("cp.async.commit_group;")
#define CP_WAIT1()  asm volatile("cp.async.wait_group 1;")
#define CP_WAIT0()  asm volatile("cp.async.wait_group 0;")

__device__ __forceinline__ void ldsm4(u32 addr, u32& r0, u32& r1, u32& r2, u32& r3) {
    asm volatile("ldmatrix.sync.aligned.m8n8.x4.shared.b16 {%0,%1,%2,%3}, [%4];"
                 : "=r"(r0), "=r"(r1), "=r"(r2), "=r"(r3) : "r"(addr));
}
// fp32-accumulate HMMA (main term)
__device__ __forceinline__ void mma_f32(float* d, const u32* a, const u32* b) {
    asm volatile("mma.sync.aligned.m16n8k16.row.col.f32.f16.f16.f32 "
                 "{%0,%1,%2,%3}, {%4,%5,%6,%7}, {%8,%9}, {%0,%1,%2,%3};"
                 : "+f"(d[0]), "+f"(d[1]), "+f"(d[2]), "+f"(d[3])
                 : "r"(a[0]), "r"(a[1]), "r"(a[2]), "r"(a[3]), "r"(b[0]), "r"(b[1]));
}
// fp16-accumulate HMMA (cross terms; values ~|15| max, rounding folded by /4096)
__device__ __forceinline__ void mma_f16(u32* d, const u32* a, const u32* b) {
    asm volatile("mma.sync.aligned.m16n8k16.row.col.f16.f16.f16.f16 "
                 "{%0,%1}, {%2,%3,%4,%5}, {%6,%7}, {%0,%1};"
                 : "+r"(d[0]), "+r"(d[1])
                 : "r"(a[0]), "r"(a[1]), "r"(a[2]), "r"(a[3]), "r"(b[0]), "r"(b[1]));
}

__device__ __forceinline__ void split2(float v, unsigned short& h0, unsigned short& h1) {
    __half a = __float2half_rn(v);
    float r = (v - __half2float(a)) * RSCALE;   // exact residual, exact pow2 scale
    __half b = __float2half_rn(r);
    h0 = __half_as_ushort(a);
    h1 = __half_as_ushort(b);
}

__device__ __forceinline__ float softplus_f(float z) {
    return (z > 0.0f) ? (z + log1pf(expf(-z))) : log1pf(expf(z));
}

// ---------------- weight pre-split kernel ----------------
__global__ void __launch_bounds__(256) split_w_kernel(const float* __restrict__ gw,
                                                      const float* __restrict__ wn) {
    __shared__ float t[64][65];
    int k0 = blockIdx.x * 64;
    for (int half = 0; half < 2; half++) {
        const float* src = half ? wn : gw;
        __syncthreads();
        for (int i = threadIdx.x; i < 64 * 64; i += 256) {
            int kk = i >> 6, n = i & 63;
            t[n][kk] = src[(size_t)(k0 + kk) * EXP + n];
        }
        __syncthreads();
        for (int i = threadIdx.x; i < 64 * 16; i += 256) {
            int n = i >> 4, c = i & 15;
            int nn = half * 64 + n;
            unsigned short h0[4], h1[4];
            #pragma unroll
            for (int j = 0; j < 4; j++) split2(t[n][c * 4 + j], h0[j], h1[j]);
            *(uint2*)&g_w0[nn][k0 + c * 4] =
                make_uint2((u32)h0[0] | ((u32)h0[1] << 16), (u32)h0[2] | ((u32)h0[3] << 16));
            *(uint2*)&g_w1[nn][k0 + c * 4] =
                make_uint2((u32)h1[0] | ((u32)h1[1] << 16), (u32)h1[2] | ((u32)h1[3] << 16));
        }
    }
}

// ---------------- main router kernel ----------------
__global__ void __launch_bounds__(THREADS, 1)
router_kernel(const float* __restrict__ x,
              const float* __restrict__ gate_b,
              const float* __restrict__ noise,
              float* __restrict__ out, int B, int nblocks)
{
    extern __shared__ __align__(1024) char smc[];
    const u32 sb = smem_u32(smc);
    float* bias_s  = (float*)(smc + CTRL_OFF);
    float* imp_s   = (float*)(smc + CTRL_OFF + 256);
    int*   load_s  = (int*)(smc + CTRL_OFF + 512);
    int*   is_last = (int*)(smc + CTRL_OFF + 768);

    const int tid = threadIdx.x;
    const int wid = tid >> 5, lane = tid & 31;
    const int m0 = blockIdx.x * MT;
    const int mwarp = wid & 3;        // 4 row groups of 32
    const int nwarp = wid >> 2;       // 4 col groups of 32

    if (tid < EXP) { bias_s[tid] = gate_b[tid]; imp_s[tid] = 0.0f; load_s[tid] = 0; }

    float accM[2][4][4];   // fp32 main accumulator, 32 regs
    u32   accC[2][4][2];   // fp16x2 cross accumulator, 16 regs
    #pragma unroll
    for (int mt = 0; mt < 2; mt++)
        #pragma unroll
        for (int nt = 0; nt < 4; nt++) {
            #pragma unroll
            for (int r = 0; r < 4; r++) accM[mt][nt][r] = 0.0f;
            accC[mt][nt][0] = 0u; accC[mt][nt][1] = 0u;
        }

    // ldmatrix lane constants
    const int a_row = lane & 15;
    const int a_kb  = lane >> 4;
    const int b_row = (lane & 7) + ((lane >> 4) & 1) * 8;
    const int b_kb  = (lane >> 3) & 1;

    // ---- prologue: issue chunk 0 into stage 0 ----
    {
        #pragma unroll
        for (int i = 0; i < 4; i++) {
            int u = tid + i * 512;
            int row = u >> 4, cu = u & 15;
            cp16(sb + XS_OFF(0) + u * 16, x + (size_t)(m0 + row) * DID + cu * 4);
        }
        #pragma unroll
        for (int i = 0; i < 2; i++) {
            int u = tid + i * 512;
            int n = u >> 3, cu = u & 7;
            u32 sw = (u32)(n * 128 + ((cu ^ (n & 7)) * 16));
            cp16(sb + B_OFF(0, 0) + sw, &g_w0[n][cu * 8]);
            cp16(sb + B_OFF(0, 1) + sw, &g_w1[n][cu * 8]);
        }
        CP_COMMIT();
    }

    for (int kc = 0; kc < NCH; kc++) {
        const int s = kc & 1;
        __syncthreads();   // all warps done with mma(kc-1): A tile free, stage s^1 free

        if (kc + 1 < NCH) {
            const int k0n = (kc + 1) * KC;
            #pragma unroll
            for (int i = 0; i < 4; i++) {
                int u = tid + i * 512;
                int row = u >> 4, cu = u & 15;
                cp16(sb + XS_OFF(s ^ 1) + u * 16, x + (size_t)(m0 + row) * DID + k0n + cu * 4);
            }
            #pragma unroll
            for (int i = 0; i < 2; i++) {
                int u = tid + i * 512;
                int n = u >> 3, cu = u & 7;
                u32 sw = (u32)(n * 128 + ((cu ^ (n & 7)) * 16));
                cp16(sb + B_OFF(s ^ 1, 0) + sw, &g_w0[n][k0n + cu * 8]);
                cp16(sb + B_OFF(s ^ 1, 1) + sw, &g_w1[n][k0n + cu * 8]);
            }
            CP_COMMIT();
            CP_WAIT1();   // chunk kc arrived
        } else {
            CP_WAIT0();
        }

        // convert x fp32 -> 2 fp16 limbs into single-stage A tiles
        #pragma unroll
        for (int i = 0; i < 4; i++) {
            int u = tid + i * 512;
            int row = u >> 4, c = u & 15;
            float4 v = *(const float4*)(smc + XS_OFF(s) + u * 16);
            unsigned short h0[4], h1[4];
            split2(v.x, h0[0], h1[0]);
            split2(v.y, h0[1], h1[1]);
            split2(v.z, h0[2], h1[2]);
            split2(v.w, h0[3], h1[3]);
            u32 off = (u32)(row * 128 + (((c >> 1) ^ (row & 7)) * 16) + (c & 1) * 8);
            *(uint2*)(smc + A_OFF(0) + off) =
                make_uint2((u32)h0[0] | ((u32)h0[1] << 16), (u32)h0[2] | ((u32)h0[3] << 16));
            *(uint2*)(smc + A_OFF(1) + off) =
                make_uint2((u32)h1[0] | ((u32)h1[1] << 16), (u32)h1[2] | ((u32)h1[3] << 16));
        }
        __syncthreads();

        // ---- mma over this chunk: 4 k-steps of 16 ----
        const u32 ab0 = sb + A_OFF(0), ab1 = sb + A_OFF(1);
        const u32 bb0 = sb + B_OFF(s, 0), bb1 = sb + B_OFF(s, 1);
        #pragma unroll
        for (int ks = 0; ks < 4; ks++) {
            u32 A0[2][4], A1[2][4];
            #pragma unroll
            for (int mt = 0; mt < 2; mt++) {
                int row = mwarp * 32 + mt * 16 + a_row;
                u32 off = (u32)(row * 128 + (((ks * 2 + a_kb) ^ (row & 7)) * 16));
                ldsm4(ab0 + off, A0[mt][0], A0[mt][1], A0[mt][2], A0[mt][3]);
                ldsm4(ab1 + off, A1[mt][0], A1[mt][1], A1[mt][2], A1[mt][3]);
            }
            u32 B0[4][2], B1[4][2];
            #pragma unroll
            for (int p = 0; p < 2; p++) {
                int n = nwarp * 32 + p * 16 + b_row;
                u32 off = (u32)(n * 128 + (((ks * 2 + b_kb) ^ (n & 7)) * 16));
                u32 r0, r1, r2, r3;
                ldsm4(bb0 + off, r0, r1, r2, r3);
                B0[p * 2][0] = r0; B0[p * 2][1] = r1; B0[p * 2 + 1][0] = r2; B0[p * 2 + 1][1] = r3;
                ldsm4(bb1 + off, r0, r1, r2, r3);
                B1[p * 2][0] = r0; B1[p * 2][1] = r1; B1[p * 2 + 1][0] = r2; B1[p * 2 + 1][1] = r3;
            }
            #pragma unroll
            for (int mt = 0; mt < 2; mt++)
                #pragma unroll
                for (int nt = 0; nt < 4; nt++) {
                    mma_f32(accM[mt][nt], A0[mt], B0[nt]);
                    mma_f16(accC[mt][nt], A0[mt], B1[nt]);
                    mma_f16(accC[mt][nt], A1[mt], B0[nt]);
                }
        }
    }

    __syncthreads();

    // ---- write combined logits to smem overlay [128][LSTRIDE] ----
    float* lsm = (float*)smc;
    {
        const int gid = lane >> 2, tig = lane & 3;
        #pragma unroll
        for (int mt = 0; mt < 2; mt++)
            #pragma unroll
            for (int nt = 0; nt < 4; nt++) {
                int r0 = mwarp * 32 + mt * 16 + gid;
                int cc = nwarp * 32 + nt * 8 + tig * 2;
                float2 c0 = __half22float2(*(__half2*)&accC[mt][nt][0]);
                float2 c1 = __half22float2(*(__half2*)&accC[mt][nt][1]);
                float f0 = fmaf(c0.x, INV_RSCALE, accM[mt][nt][0]);
                float f1 = fmaf(c0.y, INV_RSCALE, accM[mt][nt][1]);
                float f2 = fmaf(c1.x, INV_RSCALE, accM[mt][nt][2]);
                float f3 = fmaf(c1.y, INV_RSCALE, accM[mt][nt][3]);
                *(float2*)&lsm[r0 * LSTRIDE + cc]       = make_float2(f0, f1);
                *(float2*)&lsm[(r0 + 8) * LSTRIDE + cc] = make_float2(f2, f3);
            }
    }
    __syncthreads();

    // ---- epilogue: warps 0-3, one row per lane ----
    if (wid < 4) {
        const int rloc = wid * 32 + lane;
        const int row = m0 + rloc;
        const float* nrow = noise + (size_t)row * EXP;
        float l[64];
        #pragma unroll
        for (int e = 0; e < 64; e += 4) {
            float4 cl = *(const float4*)&lsm[rloc * LSTRIDE + e];
            float4 nl = *(const float4*)&lsm[rloc * LSTRIDE + 64 + e];
            float4 nz = *(const float4*)(nrow + e);
            l[e + 0] = fmaf(nz.x, softplus_f(nl.x), cl.x + bias_s[e + 0]);
            l[e + 1] = fmaf(nz.y, softplus_f(nl.y), cl.y + bias_s[e + 1]);
            l[e + 2] = fmaf(nz.z, softplus_f(nl.z), cl.z + bias_s[e + 2]);
            l[e + 3] = fmaf(nz.w, softplus_f(nl.w), cl.w + bias_s[e + 3]);
        }

        // top-2, lowest index wins ties (matches jax.lax.top_k)
        float v1 = -INFINITY, v2 = -INFINITY;
        int i1 = -1, i2 = -1;
        #pragma unroll
        for (int e = 0; e < 64; e++) {
            float le = l[e];
            if (le > v1) { v2 = v1; i2 = i1; v1 = le; i1 = e; }
            else if (le > v2) { v2 = le; i2 = e; }
        }

        // full softmax for importance
        float esum = 0.0f;
        #pragma unroll
        for (int e = 0; e < 64; e++) { l[e] = expf(l[e] - v1); esum += l[e]; }
        float inv = 1.0f / esum;

        #pragma unroll
        for (int e = 0; e < 64; e++) {
            float p = l[e] * inv;
            p += __shfl_xor_sync(0xffffffffu, p, 16);
            p += __shfl_xor_sync(0xffffffffu, p, 8);
            p += __shfl_xor_sync(0xffffffffu, p, 4);
            p += __shfl_xor_sync(0xffffffffu, p, 2);
            p += __shfl_xor_sync(0xffffffffu, p, 1);
            if (lane == 0) atomicAdd(&imp_s[e], p);
        }

        float e21 = expf(v2 - v1);
        float g1 = 1.0f / (1.0f + e21);
        float g2 = e21 * g1;
        *(float2*)(out + (size_t)row * 2) = make_float2(g1, g2);
        *(float2*)(out + (size_t)B * 2 + (size_t)row * 2) = make_float2((float)i1, (float)i2);
        atomicAdd(&load_s[i1], 1);
        atomicAdd(&load_s[i2], 1);
    }
    __syncthreads();

    if (tid < EXP) {
        atomicAdd(&g_importance[tid], imp_s[tid]);
        atomicAdd(&g_load[tid], load_s[tid]);
    }

    // last CTA: finalize aux loss + reset globals for the next graph replay
    __threadfence();
    if (tid == 0) {
        int c = atomicAdd(&g_count, 1);
        *is_last = (c == nblocks - 1) ? 1 : 0;
    }
    __syncthreads();
    if (*is_last) {
        if (tid < EXP) imp_s[tid] = g_importance[tid] * (float)g_load[tid];
        __syncthreads();
        if (tid == 0) {
            float tot = 0.0f;
            #pragma unroll
            for (int i = 0; i < EXP; i++) tot += imp_s[i];
            out[(size_t)B * 4] = tot * (float)EXP;   // mean * E^2 = sum * E
            g_count = 0;
        }
        if (tid < EXP) { g_importance[tid] = 0.0f; g_load[tid] = 0; }
    }
}

extern "C" void kernel_launch(void* const* d_in, const int* in_sizes, int n_in,
                              void* d_out, int out_size) {
    const float* x       = (const float*)d_in[0];
    const float* gate_w  = (const float*)d_in[1];
    const float* gate_b  = (const float*)d_in[2];
    const float* w_noise = (const float*)d_in[3];
    const float* noise   = (const float*)d_in[4];
    float* out = (float*)d_out;

    int B = in_sizes[0] / DID;
    int nblocks = B / MT;

    cudaFuncSetAttribute(router_kernel, cudaFuncAttributeMaxDynamicSharedMemorySize, SMEM_BYTES);

    split_w_kernel<<<DID / 64, 256>>>(gate_w, w_noise);
    router_kernel<<<nblocks, THREADS, SMEM_BYTES>>>(x, gate_b, noise, out, B, nblocks);
}

// round 8
// speedup vs baseline: 1.1410x; 1.1376x over previous
#include <cuda_runtime.h>
#include <cuda_fp16.h>
#include <math.h>

typedef unsigned int u32;

#define DID 4096
#define EXP 64
#define NE 128          // 64 clean + 64 noise output columns
#define MT 128          // rows per CTA
#define KC 64           // k per chunk
#define NCH (DID / KC)  // 64 chunks
#define THREADS 512
#define RSCALE 4096.0f
#define INV_RSCALE (1.0f / 4096.0f)

// ---------------- global scratch ----------------
__device__ unsigned short g_w0[NE][DID];   // fp16 main limb of [clean|noise] weights, [n][k]
__device__ unsigned short g_w1[NE][DID];   // fp16 residual limb (pre-scaled by 4096)
__device__ float g_importance[EXP];
__device__ int   g_load[EXP];
__device__ int   g_count;

// ---------------- smem layout (dynamic) ----------------
// [0, 64K)     A fp16 limb tiles: buf(2) x limb(2) x 16KB, swizzled [128r][64k]
// [64K, 160K)  B fp16 limb tiles: stage(3) x limb(2) x 16KB, swizzled [128n][64k]
// [160K, +1K)  control
// logits overlay [128][132] f32 = 67584B reuses [0, 67584) after the mainloop.
#define A_OFF(b, l) ((b) * 32768 + (l) * 16384)
#define B_OFF(s, l) (65536 + (s) * 32768 + (l) * 16384)
#define CTRL_OFF    163840
#define SMEM_BYTES  (163840 + 1024)
#define LSTRIDE     132

// ---------------- PTX helpers ----------------
__device__ __forceinline__ u32 smem_u32(const void* p) {
    u32 a;
    asm("{ .reg .u64 t; cvta.to.shared.u64 t, %1; cvt.u32.u64 %0, t; }" : "=r"(a) : "l"(p));
    return a;
}
__device__ __forceinline__ void cp16(u32 dst, const void* src) {
    asm volatile("cp.async.cg.shared.global [%0], [%1], 16;" :: "r"(dst), "l"(src));
}
#define CP_COMMIT() asm volatile("cp.async.commit_group;")
#define CP_WAIT1()  asm volatile("cp.async.wait_group 1;")

__device__ __forceinline__ void ldsm4(u32 addr, u32& r0, u32& r1, u32& r2, u32& r3) {
    asm volatile("ldmatrix.sync.aligned.m8n8.x4.shared.b16 {%0,%1,%2,%3}, [%4];"
                 : "=r"(r0), "=r"(r1), "=r"(r2), "=r"(r3) : "r"(addr));
}
// fp32-accumulate HMMA (main term)
__device__ __forceinline__ void mma_f32(float* d, const u32* a, const u32* b) {
    asm volatile("mma.sync.aligned.m16n8k16.row.col.f32.f16.f16.f32 "
                 "{%0,%1,%2,%3}, {%4,%5,%6,%7}, {%8,%9}, {%0,%1,%2,%3};"
                 : "+f"(d[0]), "+f"(d[1]), "+f"(d[2]), "+f"(d[3])
                 : "r"(a[0]), "r"(a[1]), "r"(a[2]), "r"(a[3]), "r"(b[0]), "r"(b[1]));
}
// fp16-accumulate HMMA (cross terms; folded by /4096 in epilogue)
__device__ __forceinline__ void mma_f16(u32* d, const u32* a, const u32* b) {
    asm volatile("mma.sync.aligned.m16n8k16.row.col.f16.f16.f16.f16 "
                 "{%0,%1}, {%2,%3,%4,%5}, {%6,%7}, {%0,%1};"
                 : "+r"(d[0]), "+r"(d[1])
                 : "r"(a[0]), "r"(a[1]), "r"(a[2]), "r"(a[3]), "r"(b[0]), "r"(b[1]));
}

// scalar split (weight pre-split kernel only)
__device__ __forceinline__ void split2(float v, unsigned short& h0, unsigned short& h1) {
    __half a = __float2half_rn(v);
    float r = (v - __half2float(a)) * RSCALE;
    __half b = __float2half_rn(r);
    h0 = __half_as_ushort(a);
    h1 = __half_as_ushort(b);
}

// vector split: float4 -> (h0 pair-packed uint2, h1 pair-packed uint2)
__device__ __forceinline__ void split2v(float4 v, uint2& m, uint2& r) {
    __half2 h0a = __floats2half2_rn(v.x, v.y);
    __half2 h0b = __floats2half2_rn(v.z, v.w);
    float2 f0a = __half22float2(h0a);
    float2 f0b = __half22float2(h0b);
    __half2 h1a = __floats2half2_rn((v.x - f0a.x) * RSCALE, (v.y - f0a.y) * RSCALE);
    __half2 h1b = __floats2half2_rn((v.z - f0b.x) * RSCALE, (v.w - f0b.y) * RSCALE);
    m.x = *(u32*)&h0a; m.y = *(u32*)&h0b;
    r.x = *(u32*)&h1a; r.y = *(u32*)&h1b;
}

__device__ __forceinline__ float softplus_f(float z) {
    return (z > 0.0f) ? (z + log1pf(expf(-z))) : log1pf(expf(z));
}

// ---------------- weight pre-split kernel ----------------
__global__ void __launch_bounds__(256) split_w_kernel(const float* __restrict__ gw,
                                                      const float* __restrict__ wn) {
    __shared__ float t[64][65];
    int k0 = blockIdx.x * 64;
    for (int half = 0; half < 2; half++) {
        const float* src = half ? wn : gw;
        __syncthreads();
        for (int i = threadIdx.x; i < 64 * 64; i += 256) {
            int kk = i >> 6, n = i & 63;
            t[n][kk] = src[(size_t)(k0 + kk) * EXP + n];
        }
        __syncthreads();
        for (int i = threadIdx.x; i < 64 * 16; i += 256) {
            int n = i >> 4, c = i & 15;
            int nn = half * 64 + n;
            unsigned short h0[4], h1[4];
            #pragma unroll
            for (int j = 0; j < 4; j++) split2(t[n][c * 4 + j], h0[j], h1[j]);
            *(uint2*)&g_w0[nn][k0 + c * 4] =
                make_uint2((u32)h0[0] | ((u32)h0[1] << 16), (u32)h0[2] | ((u32)h0[3] << 16));
            *(uint2*)&g_w1[nn][k0 + c * 4] =
                make_uint2((u32)h1[0] | ((u32)h1[1] << 16), (u32)h1[2] | ((u32)h1[3] << 16));
        }
    }
}

// ---------------- main router kernel ----------------
__global__ void __launch_bounds__(THREADS, 1)
router_kernel(const float* __restrict__ x,
              const float* __restrict__ gate_b,
              const float* __restrict__ noise,
              float* __restrict__ out, int B, int nblocks)
{
    extern __shared__ __align__(1024) char smc[];
    const u32 sb = smem_u32(smc);
    float* bias_s  = (float*)(smc + CTRL_OFF);
    float* imp_s   = (float*)(smc + CTRL_OFF + 256);
    int*   load_s  = (int*)(smc + CTRL_OFF + 512);
    int*   is_last = (int*)(smc + CTRL_OFF + 768);

    const int tid = threadIdx.x;
    const int wid = tid >> 5, lane = tid & 31;
    const int m0 = blockIdx.x * MT;
    const int mwarp = wid & 3;        // 4 row groups of 32
    const int nwarp = wid >> 2;       // 4 col groups of 32

    if (tid < EXP) { bias_s[tid] = gate_b[tid]; imp_s[tid] = 0.0f; load_s[tid] = 0; }

    float accM[2][4][4];   // fp32 main accumulator
    u32   accC[2][4][2];   // fp16x2 cross accumulator
    #pragma unroll
    for (int mt = 0; mt < 2; mt++)
        #pragma unroll
        for (int nt = 0; nt < 4; nt++) {
            #pragma unroll
            for (int r = 0; r < 4; r++) accM[mt][nt][r] = 0.0f;
            accC[mt][nt][0] = 0u; accC[mt][nt][1] = 0u;
        }

    // ldmatrix lane constants
    const int a_row = lane & 15;
    const int a_kb  = lane >> 4;
    const int b_row = (lane & 7) + ((lane >> 4) & 1) * 8;
    const int b_kb  = (lane >> 3) & 1;

    // per-thread x mapping: u = tid + i*512 -> row = u>>4, c = u&15 (float4 col)
    const int xrow[4] = { (tid) >> 4, (tid + 512) >> 4, (tid + 1024) >> 4, (tid + 1536) >> 4 };
    const int xc[4]   = { tid & 15, (tid + 512) & 15, (tid + 1024) & 15, (tid + 1536) & 15 };
    u32 asw[4];
    #pragma unroll
    for (int i = 0; i < 4; i++) {
        int row = xrow[i], c = xc[i];
        asw[i] = (u32)(row * 128 + (((c >> 1) ^ (row & 7)) * 16) + (c & 1) * 8);
    }

    float4 xr[4];

    // ---- prologue ----
    {
        // LDG x(0)
        #pragma unroll
        for (int i = 0; i < 4; i++)
            xr[i] = *(const float4*)(x + (size_t)(m0 + xrow[i]) * DID + xc[i] * 4);
        // cp B(0), B(1) as two groups
        #pragma unroll
        for (int s = 0; s < 2; s++) {
            const int k0 = s * KC;
            #pragma unroll
            for (int i = 0; i < 2; i++) {
                int u = tid + i * 512;
                int n = u >> 3, cu = u & 7;
                u32 sw = (u32)(n * 128 + ((cu ^ (n & 7)) * 16));
                cp16(sb + B_OFF(s, 0) + sw, &g_w0[n][k0 + cu * 8]);
                cp16(sb + B_OFF(s, 1) + sw, &g_w1[n][k0 + cu * 8]);
            }
            CP_COMMIT();
        }
        // convert x(0) -> A buf 0
        #pragma unroll
        for (int i = 0; i < 4; i++) {
            uint2 m, r;
            split2v(xr[i], m, r);
            *(uint2*)(smc + A_OFF(0, 0) + asw[i]) = m;
            *(uint2*)(smc + A_OFF(0, 1) + asw[i]) = r;
        }
        // LDG x(1)
        #pragma unroll
        for (int i = 0; i < 4; i++)
            xr[i] = *(const float4*)(x + (size_t)(m0 + xrow[i]) * DID + KC + xc[i] * 4);
        CP_WAIT1();   // B(0) ready
        __syncthreads();
    }

    int s3 = 0;   // B stage of current chunk (kc % 3)
    #pragma unroll 1
    for (int kc = 0; kc < NCH; kc++) {
        const int ab = kc & 1;

        // issue cp for B(kc+2) into stage (kc+2)%3 — always commit (group may be empty)
        if (kc + 2 < NCH) {
            int s_cp = s3 + 2; if (s_cp >= 3) s_cp -= 3;
            const int k0n = (kc + 2) * KC;
            #pragma unroll
            for (int i = 0; i < 2; i++) {
                int u = tid + i * 512;
                int n = u >> 3, cu = u & 7;
                u32 sw = (u32)(n * 128 + ((cu ^ (n & 7)) * 16));
                cp16(sb + B_OFF(s_cp, 0) + sw, &g_w0[n][k0n + cu * 8]);
                cp16(sb + B_OFF(s_cp, 1) + sw, &g_w1[n][k0n + cu * 8]);
            }
        }
        CP_COMMIT();

        // convert x(kc+1) -> A buf ab^1 (overlaps tensor-pipe drain of chunk kc-1 / issue of kc)
        if (kc + 1 < NCH) {
            #pragma unroll
            for (int i = 0; i < 4; i++) {
                uint2 m, r;
                split2v(xr[i], m, r);
                *(uint2*)(smc + A_OFF(ab ^ 1, 0) + asw[i]) = m;
                *(uint2*)(smc + A_OFF(ab ^ 1, 1) + asw[i]) = r;
            }
        }
        // LDG x(kc+2)
        if (kc + 2 < NCH) {
            const int k0n = (kc + 2) * KC;
            #pragma unroll
            for (int i = 0; i < 4; i++)
                xr[i] = *(const float4*)(x + (size_t)(m0 + xrow[i]) * DID + k0n + xc[i] * 4);
        }

        // ---- mma over chunk kc: 4 k-steps of 16 ----
        const u32 ab0 = sb + A_OFF(ab, 0), ab1 = sb + A_OFF(ab, 1);
        const u32 bb0 = sb + B_OFF(s3, 0), bb1 = sb + B_OFF(s3, 1);
        #pragma unroll
        for (int ks = 0; ks < 4; ks++) {
            u32 A0[2][4], A1[2][4];
            #pragma unroll
            for (int mt = 0; mt < 2; mt++) {
                int row = mwarp * 32 + mt * 16 + a_row;
                u32 off = (u32)(row * 128 + (((ks * 2 + a_kb) ^ (row & 7)) * 16));
                ldsm4(ab0 + off, A0[mt][0], A0[mt][1], A0[mt][2], A0[mt][3]);
                ldsm4(ab1 + off, A1[mt][0], A1[mt][1], A1[mt][2], A1[mt][3]);
            }
            u32 B0[4][2], B1[4][2];
            #pragma unroll
            for (int p = 0; p < 2; p++) {
                int n = nwarp * 32 + p * 16 + b_row;
                u32 off = (u32)(n * 128 + (((ks * 2 + b_kb) ^ (n & 7)) * 16));
                u32 r0, r1, r2, r3;
                ldsm4(bb0 + off, r0, r1, r2, r3);
                B0[p * 2][0] = r0; B0[p * 2][1] = r1; B0[p * 2 + 1][0] = r2; B0[p * 2 + 1][1] = r3;
                ldsm4(bb1 + off, r0, r1, r2, r3);
                B1[p * 2][0] = r0; B1[p * 2][1] = r1; B1[p * 2 + 1][0] = r2; B1[p * 2 + 1][1] = r3;
            }
            #pragma unroll
            for (int mt = 0; mt < 2; mt++)
                #pragma unroll
                for (int nt = 0; nt < 4; nt++) {
                    mma_f32(accM[mt][nt], A0[mt], B0[nt]);
                    mma_f16(accC[mt][nt], A0[mt], B1[nt]);
                    mma_f16(accC[mt][nt], A1[mt], B0[nt]);
                }
        }

        CP_WAIT1();   // B(kc+1) ready (only the newest group may be outstanding)
        __syncthreads();

        s3 = (s3 == 2) ? 0 : s3 + 1;
    }

    // ---- write combined logits to smem overlay [128][LSTRIDE] ----
    float* lsm = (float*)smc;
    {
        const int gid = lane >> 2, tig = lane & 3;
        #pragma unroll
        for (int mt = 0; mt < 2; mt++)
            #pragma unroll
            for (int nt = 0; nt < 4; nt++) {
                int r0 = mwarp * 32 + mt * 16 + gid;
                int cc = nwarp * 32 + nt * 8 + tig * 2;
                float2 c0 = __half22float2(*(__half2*)&accC[mt][nt][0]);
                float2 c1 = __half22float2(*(__half2*)&accC[mt][nt][1]);
                float f0 = fmaf(c0.x, INV_RSCALE, accM[mt][nt][0]);
                float f1 = fmaf(c0.y, INV_RSCALE, accM[mt][nt][1]);
                float f2 = fmaf(c1.x, INV_RSCALE, accM[mt][nt][2]);
                float f3 = fmaf(c1.y, INV_RSCALE, accM[mt][nt][3]);
                *(float2*)&lsm[r0 * LSTRIDE + cc]       = make_float2(f0, f1);
                *(float2*)&lsm[(r0 + 8) * LSTRIDE + cc] = make_float2(f2, f3);
            }
    }
    __syncthreads();

    // ---- epilogue: warps 0-3, one row per lane ----
    if (wid < 4) {
        const int rloc = wid * 32 + lane;
        const int row = m0 + rloc;
        const float* nrow = noise + (size_t)row * EXP;
        float l[64];
        #pragma unroll
        for (int e = 0; e < 64; e += 4) {
            float4 cl = *(const float4*)&lsm[rloc * LSTRIDE + e];
            float4 nl = *(const float4*)&lsm[rloc * LSTRIDE + 64 + e];
            float4 nz = *(const float4*)(nrow + e);
            l[e + 0] = fmaf(nz.x, softplus_f(nl.x), cl.x + bias_s[e + 0]);
            l[e + 1] = fmaf(nz.y, softplus_f(nl.y), cl.y + bias_s[e + 1]);
            l[e + 2] = fmaf(nz.z, softplus_f(nl.z), cl.z + bias_s[e + 2]);
            l[e + 3] = fmaf(nz.w, softplus_f(nl.w), cl.w + bias_s[e + 3]);
        }

        // top-2, lowest index wins ties (matches jax.lax.top_k)
        float v1 = -INFINITY, v2 = -INFINITY;
        int i1 = -1, i2 = -1;
        #pragma unroll
        for (int e = 0; e < 64; e++) {
            float le = l[e];
            if (le > v1) { v2 = v1; i2 = i1; v1 = le; i1 = e; }
            else if (le > v2) { v2 = le; i2 = e; }
        }

        // full softmax for importance
        float esum = 0.0f;
        #pragma unroll
        for (int e = 0; e < 64; e++) { l[e] = expf(l[e] - v1); esum += l[e]; }
        float inv = 1.0f / esum;

        #pragma unroll
        for (int e = 0; e < 64; e++) {
            float p = l[e] * inv;
            p += __shfl_xor_sync(0xffffffffu, p, 16);
            p += __shfl_xor_sync(0xffffffffu, p, 8);
            p += __shfl_xor_sync(0xffffffffu, p, 4);
            p += __shfl_xor_sync(0xffffffffu, p, 2);
            p += __shfl_xor_sync(0xffffffffu, p, 1);
            if (lane == 0) atomicAdd(&imp_s[e], p);
        }

        float e21 = expf(v2 - v1);
        float g1 = 1.0f / (1.0f + e21);
        float g2 = e21 * g1;
        *(float2*)(out + (size_t)row * 2) = make_float2(g1, g2);
        *(float2*)(out + (size_t)B * 2 + (size_t)row * 2) = make_float2((float)i1, (float)i2);
        atomicAdd(&load_s[i1], 1);
        atomicAdd(&load_s[i2], 1);
    }
    __syncthreads();

    if (tid < EXP) {
        atomicAdd(&g_importance[tid], imp_s[tid]);
        atomicAdd(&g_load[tid], load_s[tid]);
    }

    // last CTA: finalize aux loss + reset globals for the next graph replay
    __threadfence();
    if (tid == 0) {
        int c = atomicAdd(&g_count, 1);
        *is_last = (c == nblocks - 1) ? 1 : 0;
    }
    __syncthreads();
    if (*is_last) {
        if (tid < EXP) imp_s[tid] = g_importance[tid] * (float)g_load[tid];
        __syncthreads();
        if (tid == 0) {
            float tot = 0.0f;
            #pragma unroll
            for (int i = 0; i < EXP; i++) tot += imp_s[i];
            out[(size_t)B * 4] = tot * (float)EXP;   // mean * E^2 = sum * E
            g_count = 0;
        }
        if (tid < EXP) { g_importance[tid] = 0.0f; g_load[tid] = 0; }
    }
}

extern "C" void kernel_launch(void* const* d_in, const int* in_sizes, int n_in,
                              void* d_out, int out_size) {
    const float* x       = (const float*)d_in[0];
    const float* gate_w  = (const float*)d_in[1];
    const float* gate_b  = (const float*)d_in[2];
    const float* w_noise = (const float*)d_in[3];
    const float* noise   = (const float*)d_in[4];
    float* out = (float*)d_out;

    int B = in_sizes[0] / DID;
    int nblocks = B / MT;

    cudaFuncSetAttribute(router_kernel, cudaFuncAttributeMaxDynamicSharedMemorySize, SMEM_BYTES);

    split_w_kernel<<<DID / 64, 256>>>(gate_w, w_noise);
    router_kernel<<<nblocks, THREADS, SMEM_BYTES>>>(x, gate_b, noise, out, B, nblocks);
}

// round 9
// speedup vs baseline: 1.2631x; 1.1070x over previous
#include <cuda_runtime.h>
#include <cuda_fp16.h>
#include <math.h>

typedef unsigned int u32;

#define DID 4096
#define EXP 64
#define NE 128          // 64 clean + 64 noise output columns
#define MT 64           // rows per CTA
#define KC 64           // k per chunk
#define NCH (DID / KC)  // 64 chunks
#define THREADS 256
#define RSCALE 4096.0f
#define INV_RSCALE (1.0f / 4096.0f)

// ---------------- global scratch ----------------
__device__ unsigned short g_w0[NE][DID];   // fp16 main limb of [clean|noise] weights, [n][k]
__device__ unsigned short g_w1[NE][DID];   // fp16 residual limb (pre-scaled by 4096)
__device__ float g_importance[EXP];
__device__ int   g_load[EXP];
__device__ int   g_count;

// ---------------- smem layout (dynamic, per CTA 97.3KB -> 2 CTAs/SM) ----------------
// [0, 32K)    A fp16 limb tiles: buf(2) x limb(2) x 8KB, swizzled [64r][64k]
// [32K, 96K)  B fp16 limb tiles: stage(2) x limb(2) x 16KB, swizzled [128n][64k]
// [96K, +1K)  control
// logits overlay [64][132] f32 = 33.8KB reuses [0, 33.8K) after the mainloop.
#define A_OFF(b, l) ((b) * 16384 + (l) * 8192)
#define B_OFF(s, l) (32768 + (s) * 32768 + (l) * 16384)
#define CTRL_OFF    98304
#define SMEM_BYTES  (98304 + 1024)
#define LSTRIDE     132

// ---------------- PTX helpers ----------------
__device__ __forceinline__ u32 smem_u32(const void* p) {
    u32 a;
    asm("{ .reg .u64 t; cvta.to.shared.u64 t, %1; cvt.u32.u64 %0, t; }" : "=r"(a) : "l"(p));
    return a;
}
__device__ __forceinline__ void cp16(u32 dst, const void* src) {
    asm volatile("cp.async.cg.shared.global [%0], [%1], 16;" :: "r"(dst), "l"(src));
}
#define CP_COMMIT() asm volatile("cp.async.commit_group;")
#define CP_WAIT1()  asm volatile("cp.async.wait_group 1;")
#define CP_WAIT0()  asm volatile("cp.async.wait_group 0;")

__device__ __forceinline__ void ldsm4(u32 addr, u32& r0, u32& r1, u32& r2, u32& r3) {
    asm volatile("ldmatrix.sync.aligned.m8n8.x4.shared.b16 {%0,%1,%2,%3}, [%4];"
                 : "=r"(r0), "=r"(r1), "=r"(r2), "=r"(r3) : "r"(addr));
}
// fp32-accumulate HMMA (main term)
__device__ __forceinline__ void mma_f32(float* d, const u32* a, const u32* b) {
    asm volatile("mma.sync.aligned.m16n8k16.row.col.f32.f16.f16.f32 "
                 "{%0,%1,%2,%3}, {%4,%5,%6,%7}, {%8,%9}, {%0,%1,%2,%3};"
                 : "+f"(d[0]), "+f"(d[1]), "+f"(d[2]), "+f"(d[3])
                 : "r"(a[0]), "r"(a[1]), "r"(a[2]), "r"(a[3]), "r"(b[0]), "r"(b[1]));
}
// fp16-accumulate HMMA (cross terms; folded by /4096 in epilogue)
__device__ __forceinline__ void mma_f16(u32* d, const u32* a, const u32* b) {
    asm volatile("mma.sync.aligned.m16n8k16.row.col.f16.f16.f16.f16 "
                 "{%0,%1}, {%2,%3,%4,%5}, {%6,%7}, {%0,%1};"
                 : "+r"(d[0]), "+r"(d[1])
                 : "r"(a[0]), "r"(a[1]), "r"(a[2]), "r"(a[3]), "r"(b[0]), "r"(b[1]));
}

// scalar split (weight pre-split kernel only)
__device__ __forceinline__ void split2(float v, unsigned short& h0, unsigned short& h1) {
    __half a = __float2half_rn(v);
    float r = (v - __half2float(a)) * RSCALE;
    __half b = __float2half_rn(r);
    h0 = __half_as_ushort(a);
    h1 = __half_as_ushort(b);
}

// vector split: float4 -> (h0 pair-packed uint2, h1 pair-packed uint2)
__device__ __forceinline__ void split2v(float4 v, uint2& m, uint2& r) {
    __half2 h0a = __floats2half2_rn(v.x, v.y);
    __half2 h0b = __floats2half2_rn(v.z, v.w);
    float2 f0a = __half22float2(h0a);
    float2 f0b = __half22float2(h0b);
    __half2 h1a = __floats2half2_rn((v.x - f0a.x) * RSCALE, (v.y - f0a.y) * RSCALE);
    __half2 h1b = __floats2half2_rn((v.z - f0b.x) * RSCALE, (v.w - f0b.y) * RSCALE);
    m.x = *(u32*)&h0a; m.y = *(u32*)&h0b;
    r.x = *(u32*)&h1a; r.y = *(u32*)&h1b;
}

__device__ __forceinline__ float softplus_f(float z) {
    return (z > 0.0f) ? (z + log1pf(expf(-z))) : log1pf(expf(z));
}

// ---------------- weight pre-split kernel ----------------
__global__ void __launch_bounds__(256) split_w_kernel(const float* __restrict__ gw,
                                                      const float* __restrict__ wn) {
    __shared__ float t[64][65];
    int k0 = blockIdx.x * 64;
    for (int half = 0; half < 2; half++) {
        const float* src = half ? wn : gw;
        __syncthreads();
        for (int i = threadIdx.x; i < 64 * 64; i += 256) {
            int kk = i >> 6, n = i & 63;
            t[n][kk] = src[(size_t)(k0 + kk) * EXP + n];
        }
        __syncthreads();
        for (int i = threadIdx.x; i < 64 * 16; i += 256) {
            int n = i >> 4, c = i & 15;
            int nn = half * 64 + n;
            unsigned short h0[4], h1[4];
            #pragma unroll
            for (int j = 0; j < 4; j++) split2(t[n][c * 4 + j], h0[j], h1[j]);
            *(uint2*)&g_w0[nn][k0 + c * 4] =
                make_uint2((u32)h0[0] | ((u32)h0[1] << 16), (u32)h0[2] | ((u32)h0[3] << 16));
            *(uint2*)&g_w1[nn][k0 + c * 4] =
                make_uint2((u32)h1[0] | ((u32)h1[1] << 16), (u32)h1[2] | ((u32)h1[3] << 16));
        }
    }
}

// ---------------- main router kernel ----------------
__global__ void __launch_bounds__(THREADS, 2)
router_kernel(const float* __restrict__ x,
              const float* __restrict__ gate_b,
              const float* __restrict__ noise,
              float* __restrict__ out, int B, int nblocks)
{
    extern __shared__ __align__(1024) char smc[];
    const u32 sb = smem_u32(smc);
    float* bias_s  = (float*)(smc + CTRL_OFF);
    float* imp_s   = (float*)(smc + CTRL_OFF + 256);
    int*   load_s  = (int*)(smc + CTRL_OFF + 512);
    int*   is_last = (int*)(smc + CTRL_OFF + 768);

    const int tid = threadIdx.x;
    const int wid = tid >> 5, lane = tid & 31;
    const int m0 = blockIdx.x * MT;
    const int mwarp = wid & 1;        // 2 row groups of 32
    const int nwarp = wid >> 1;       // 4 col groups of 32

    if (tid < EXP) { bias_s[tid] = gate_b[tid]; imp_s[tid] = 0.0f; load_s[tid] = 0; }

    float accM[2][4][4];   // fp32 main accumulator
    u32   accC[2][4][2];   // fp16x2 cross accumulator
    #pragma unroll
    for (int mt = 0; mt < 2; mt++)
        #pragma unroll
        for (int nt = 0; nt < 4; nt++) {
            #pragma unroll
            for (int r = 0; r < 4; r++) accM[mt][nt][r] = 0.0f;
            accC[mt][nt][0] = 0u; accC[mt][nt][1] = 0u;
        }

    // ldmatrix lane constants
    const int a_row = lane & 15;
    const int a_kb  = lane >> 4;
    const int b_row = (lane & 7) + ((lane >> 4) & 1) * 8;
    const int b_kb  = (lane >> 3) & 1;

    // per-thread x mapping: u = tid + i*256 -> row = u>>4 (0..63), c = u&15 (float4 col)
    int xrow[4], xc[4];
    u32 asw[4];
    #pragma unroll
    for (int i = 0; i < 4; i++) {
        int u = tid + i * 256;
        xrow[i] = u >> 4; xc[i] = u & 15;
        asw[i] = (u32)(xrow[i] * 128 + (((xc[i] >> 1) ^ (xrow[i] & 7)) * 16) + (xc[i] & 1) * 8);
    }

    float4 xr[4];

    // ---- prologue ----
    {
        // LDG x(0)
        #pragma unroll
        for (int i = 0; i < 4; i++)
            xr[i] = *(const float4*)(x + (size_t)(m0 + xrow[i]) * DID + xc[i] * 4);
        // cp B(0) into stage 0
        #pragma unroll
        for (int i = 0; i < 4; i++) {
            int u = tid + i * 256;
            int n = u >> 3, cu = u & 7;
            u32 sw = (u32)(n * 128 + ((cu ^ (n & 7)) * 16));
            cp16(sb + B_OFF(0, 0) + sw, &g_w0[n][cu * 8]);
            cp16(sb + B_OFF(0, 1) + sw, &g_w1[n][cu * 8]);
        }
        CP_COMMIT();
        // convert x(0) -> A buf 0
        #pragma unroll
        for (int i = 0; i < 4; i++) {
            uint2 m, r;
            split2v(xr[i], m, r);
            *(uint2*)(smc + A_OFF(0, 0) + asw[i]) = m;
            *(uint2*)(smc + A_OFF(0, 1) + asw[i]) = r;
        }
        // LDG x(1)
        #pragma unroll
        for (int i = 0; i < 4; i++)
            xr[i] = *(const float4*)(x + (size_t)(m0 + xrow[i]) * DID + KC + xc[i] * 4);
        CP_WAIT0();   // B(0) ready
        __syncthreads();
    }

    #pragma unroll 1
    for (int kc = 0; kc < NCH; kc++) {
        const int ab = kc & 1;
        const int s  = kc & 1;

        // issue cp for B(kc+1) into the other stage
        if (kc + 1 < NCH) {
            const int k0n = (kc + 1) * KC;
            #pragma unroll
            for (int i = 0; i < 4; i++) {
                int u = tid + i * 256;
                int n = u >> 3, cu = u & 7;
                u32 sw = (u32)(n * 128 + ((cu ^ (n & 7)) * 16));
                cp16(sb + B_OFF(s ^ 1, 0) + sw, &g_w0[n][k0n + cu * 8]);
                cp16(sb + B_OFF(s ^ 1, 1) + sw, &g_w1[n][k0n + cu * 8]);
            }
        }
        CP_COMMIT();

        // convert x(kc+1) -> A buf ab^1 (overlaps tensor drain; other CTA covers rest)
        if (kc + 1 < NCH) {
            #pragma unroll
            for (int i = 0; i < 4; i++) {
                uint2 m, r;
                split2v(xr[i], m, r);
                *(uint2*)(smc + A_OFF(ab ^ 1, 0) + asw[i]) = m;
                *(uint2*)(smc + A_OFF(ab ^ 1, 1) + asw[i]) = r;
            }
        }
        // LDG x(kc+2)
        if (kc + 2 < NCH) {
            const int k0n = (kc + 2) * KC;
            #pragma unroll
            for (int i = 0; i < 4; i++)
                xr[i] = *(const float4*)(x + (size_t)(m0 + xrow[i]) * DID + k0n + xc[i] * 4);
        }

        // ---- mma over chunk kc: 4 k-steps of 16 ----
        const u32 ab0 = sb + A_OFF(ab, 0), ab1 = sb + A_OFF(ab, 1);
        const u32 bb0 = sb + B_OFF(s, 0), bb1 = sb + B_OFF(s, 1);
        #pragma unroll
        for (int ks = 0; ks < 4; ks++) {
            u32 A0[2][4], A1[2][4];
            #pragma unroll
            for (int mt = 0; mt < 2; mt++) {
                int row = mwarp * 32 + mt * 16 + a_row;
                u32 off = (u32)(row * 128 + (((ks * 2 + a_kb) ^ (row & 7)) * 16));
                ldsm4(ab0 + off, A0[mt][0], A0[mt][1], A0[mt][2], A0[mt][3]);
                ldsm4(ab1 + off, A1[mt][0], A1[mt][1], A1[mt][2], A1[mt][3]);
            }
            u32 B0[4][2], B1[4][2];
            #pragma unroll
            for (int p = 0; p < 2; p++) {
                int n = nwarp * 32 + p * 16 + b_row;
                u32 off = (u32)(n * 128 + (((ks * 2 + b_kb) ^ (n & 7)) * 16));
                u32 r0, r1, r2, r3;
                ldsm4(bb0 + off, r0, r1, r2, r3);
                B0[p * 2][0] = r0; B0[p * 2][1] = r1; B0[p * 2 + 1][0] = r2; B0[p * 2 + 1][1] = r3;
                ldsm4(bb1 + off, r0, r1, r2, r3);
                B1[p * 2][0] = r0; B1[p * 2][1] = r1; B1[p * 2 + 1][0] = r2; B1[p * 2 + 1][1] = r3;
            }
            #pragma unroll
            for (int mt = 0; mt < 2; mt++)
                #pragma unroll
                for (int nt = 0; nt < 4; nt++) {
                    mma_f32(accM[mt][nt], A0[mt], B0[nt]);
                    mma_f16(accC[mt][nt], A0[mt], B1[nt]);
                    mma_f16(accC[mt][nt], A1[mt], B0[nt]);
                }
        }

        CP_WAIT1();     // ensure B(kc+1) landed (only newest group may remain)
        __syncthreads();
    }

    // ---- write combined logits to smem overlay [64][LSTRIDE] ----
    float* lsm = (float*)smc;
    {
        const int gid = lane >> 2, tig = lane & 3;
        #pragma unroll
        for (int mt = 0; mt < 2; mt++)
            #pragma unroll
            for (int nt = 0; nt < 4; nt++) {
                int r0 = mwarp * 32 + mt * 16 + gid;
                int cc = nwarp * 32 + nt * 8 + tig * 2;
                float2 c0 = __half22float2(*(__half2*)&accC[mt][nt][0]);
                float2 c1 = __half22float2(*(__half2*)&accC[mt][nt][1]);
                float f0 = fmaf(c0.x, INV_RSCALE, accM[mt][nt][0]);
                float f1 = fmaf(c0.y, INV_RSCALE, accM[mt][nt][1]);
                float f2 = fmaf(c1.x, INV_RSCALE, accM[mt][nt][2]);
                float f3 = fmaf(c1.y, INV_RSCALE, accM[mt][nt][3]);
                *(float2*)&lsm[r0 * LSTRIDE + cc]       = make_float2(f0, f1);
                *(float2*)&lsm[(r0 + 8) * LSTRIDE + cc] = make_float2(f2, f3);
            }
    }
    __syncthreads();

    // ---- epilogue: warps 0-1, one row per lane ----
    if (wid < 2) {
        const int rloc = wid * 32 + lane;
        const int row = m0 + rloc;
        const float* nrow = noise + (size_t)row * EXP;
        float l[64];
        #pragma unroll
        for (int e = 0; e < 64; e += 4) {
            float4 cl = *(const float4*)&lsm[rloc * LSTRIDE + e];
            float4 nl = *(const float4*)&lsm[rloc * LSTRIDE + 64 + e];
            float4 nz = *(const float4*)(nrow + e);
            l[e + 0] = fmaf(nz.x, softplus_f(nl.x), cl.x + bias_s[e + 0]);
            l[e + 1] = fmaf(nz.y, softplus_f(nl.y), cl.y + bias_s[e + 1]);
            l[e + 2] = fmaf(nz.z, softplus_f(nl.z), cl.z + bias_s[e + 2]);
            l[e + 3] = fmaf(nz.w, softplus_f(nl.w), cl.w + bias_s[e + 3]);
        }

        // top-2, lowest index wins ties (matches jax.lax.top_k)
        float v1 = -INFINITY, v2 = -INFINITY;
        int i1 = -1, i2 = -1;
        #pragma unroll
        for (int e = 0; e < 64; e++) {
            float le = l[e];
            if (le > v1) { v2 = v1; i2 = i1; v1 = le; i1 = e; }
            else if (le > v2) { v2 = le; i2 = e; }
        }

        // full softmax for importance
        float esum = 0.0f;
        #pragma unroll
        for (int e = 0; e < 64; e++) { l[e] = expf(l[e] - v1); esum += l[e]; }
        float inv = 1.0f / esum;

        #pragma unroll
        for (int e = 0; e < 64; e++) {
            float p = l[e] * inv;
            p += __shfl_xor_sync(0xffffffffu, p, 16);
            p += __shfl_xor_sync(0xffffffffu, p, 8);
            p += __shfl_xor_sync(0xffffffffu, p, 4);
            p += __shfl_xor_sync(0xffffffffu, p, 2);
            p += __shfl_xor_sync(0xffffffffu, p, 1);
            if (lane == 0) atomicAdd(&imp_s[e], p);
        }

        float e21 = expf(v2 - v1);
        float g1 = 1.0f / (1.0f + e21);
        float g2 = e21 * g1;
        *(float2*)(out + (size_t)row * 2) = make_float2(g1, g2);
        *(float2*)(out + (size_t)B * 2 + (size_t)row * 2) = make_float2((float)i1, (float)i2);
        atomicAdd(&load_s[i1], 1);
        atomicAdd(&load_s[i2], 1);
    }
    __syncthreads();

    if (tid < EXP) {
        atomicAdd(&g_importance[tid], imp_s[tid]);
        atomicAdd(&g_load[tid], load_s[tid]);
    }

    // last CTA: finalize aux loss + reset globals for the next graph replay
    __threadfence();
    if (tid == 0) {
        int c = atomicAdd(&g_count, 1);
        *is_last = (c == nblocks - 1) ? 1 : 0;
    }
    __syncthreads();
    if (*is_last) {
        if (tid < EXP) imp_s[tid] = g_importance[tid] * (float)g_load[tid];
        __syncthreads();
        if (tid == 0) {
            float tot = 0.0f;
            #pragma unroll
            for (int i = 0; i < EXP; i++) tot += imp_s[i];
            out[(size_t)B * 4] = tot * (float)EXP;   // mean * E^2 = sum * E
            g_count = 0;
        }
        if (tid < EXP) { g_importance[tid] = 0.0f; g_load[tid] = 0; }
    }
}

extern "C" void kernel_launch(void* const* d_in, const int* in_sizes, int n_in,
                              void* d_out, int out_size) {
    const float* x       = (const float*)d_in[0];
    const float* gate_w  = (const float*)d_in[1];
    const float* gate_b  = (const float*)d_in[2];
    const float* w_noise = (const float*)d_in[3];
    const float* noise   = (const float*)d_in[4];
    float* out = (float*)d_out;

    int B = in_sizes[0] / DID;
    int nblocks = B / MT;

    cudaFuncSetAttribute(router_kernel, cudaFuncAttributeMaxDynamicSharedMemorySize, SMEM_BYTES);

    split_w_kernel<<<DID / 64, 256>>>(gate_w, w_noise);
    router_kernel<<<nblocks, THREADS, SMEM_BYTES>>>(x, gate_b, noise, out, B, nblocks);
}